// round 1
// baseline (speedup 1.0000x reference)
#include <cuda_runtime.h>
#include <math.h>

// Problem constants
#define CB 4
#define CT 2048
#define CD 1024
#define CH 8
#define CHD 128
#define CM (CB * CT)          // 8192 rows
#define YTOT (CM * CD)        // 8388608
#define STOT (CB * CH * CHD * CHD)  // 524288
#define RES_SCALE 0.5f

// -------------------- scratch (device globals; no allocations allowed) ----
__device__ float g_h[CM * CD];
__device__ float g_q[CM * CD];
__device__ float g_k[CM * CD];
__device__ float g_v[CM * CD];
__device__ float g_gate[CM * CD];
__device__ float g_o[CM * CD];
__device__ float g_attn[CM * CD];
__device__ float g_x1[CM * CD];
__device__ float g_h2[CM * CD];
__device__ float g_m2[CM * CD];
__device__ float g_mlp[CM * 4 * CD];
__device__ float g_beta[CM * CH];
__device__ float g_eg[CM * CH];
__device__ float g_sfdummy[STOT];

// -------------------- helpers --------------------------------------------
__device__ __forceinline__ float siluf(float x) { return x / (1.0f + expf(-x)); }

__device__ __forceinline__ float warpAllSum(float v) {
    v += __shfl_xor_sync(0xffffffffu, v, 16);
    v += __shfl_xor_sync(0xffffffffu, v, 8);
    v += __shfl_xor_sync(0xffffffffu, v, 4);
    v += __shfl_xor_sync(0xffffffffu, v, 2);
    v += __shfl_xor_sync(0xffffffffu, v, 1);
    return v;
}

// -------------------- rmsnorm over D=1024, one block per row --------------
__global__ void rmsnorm_k(const float* __restrict__ x, const float* __restrict__ w,
                          float* __restrict__ out) {
    int row = blockIdx.x;
    int tid = threadIdx.x;             // 256 threads, float4 each
    const float4* x4 = (const float4*)(x + (size_t)row * CD);
    const float4* w4 = (const float4*)w;
    float4 v = x4[tid];
    float ss = v.x * v.x + v.y * v.y + v.z * v.z + v.w * v.w;
    // block reduce
    __shared__ float red[8];
    int lane = tid & 31, warp = tid >> 5;
    ss = warpAllSum(ss);
    if (lane == 0) red[warp] = ss;
    __syncthreads();
    float tot = red[0] + red[1] + red[2] + red[3] + red[4] + red[5] + red[6] + red[7];
    float sc = rsqrtf(tot * (1.0f / CD) + 1e-6f);
    float4 wv = w4[tid];
    float4 o;
    o.x = v.x * wv.x * sc; o.y = v.y * wv.y * sc;
    o.z = v.z * wv.z * sc; o.w = v.w * wv.w * sc;
    ((float4*)(out + (size_t)row * CD))[tid] = o;
}

// -------------------- x1 = x + a*0.5 ; h2 = rmsnorm(x1, w) ----------------
__global__ void resid_rms_k(const float* __restrict__ x, const float* __restrict__ a,
                            const float* __restrict__ w,
                            float* __restrict__ x1, float* __restrict__ h2) {
    int row = blockIdx.x;
    int tid = threadIdx.x;
    const float4* x4 = (const float4*)(x + (size_t)row * CD);
    const float4* a4 = (const float4*)(a + (size_t)row * CD);
    float4 xv = x4[tid], av = a4[tid];
    float4 v;
    v.x = xv.x + RES_SCALE * av.x; v.y = xv.y + RES_SCALE * av.y;
    v.z = xv.z + RES_SCALE * av.z; v.w = xv.w + RES_SCALE * av.w;
    ((float4*)(x1 + (size_t)row * CD))[tid] = v;
    float ss = v.x * v.x + v.y * v.y + v.z * v.z + v.w * v.w;
    __shared__ float red[8];
    int lane = tid & 31, warp = tid >> 5;
    ss = warpAllSum(ss);
    if (lane == 0) red[warp] = ss;
    __syncthreads();
    float tot = red[0] + red[1] + red[2] + red[3] + red[4] + red[5] + red[6] + red[7];
    float sc = rsqrtf(tot * (1.0f / CD) + 1e-6f);
    float4 wv = ((const float4*)w)[tid];
    float4 o;
    o.x = v.x * wv.x * sc; o.y = v.y * wv.y * sc;
    o.z = v.z * wv.z * sc; o.w = v.w * wv.w * sc;
    ((float4*)(h2 + (size_t)row * CD))[tid] = o;
}

// -------------------- y = x1 + m2*0.5 (to d_out) --------------------------
__global__ void final_add_k(const float* __restrict__ x1, const float* __restrict__ m2,
                            float* __restrict__ y) {
    int i = blockIdx.x * blockDim.x + threadIdx.x;
    float4 a = ((const float4*)x1)[i];
    float4 b = ((const float4*)m2)[i];
    float4 o;
    o.x = a.x + RES_SCALE * b.x; o.y = a.y + RES_SCALE * b.y;
    o.z = a.z + RES_SCALE * b.z; o.w = a.w + RES_SCALE * b.w;
    ((float4*)y)[i] = o;
}

// -------------------- generic fp32 GEMM, 128x128 tile, 8x8/thread --------
template <bool DOSILU>
__global__ __launch_bounds__(256, 2) void sgemm128(
    const float* __restrict__ A, const float* __restrict__ B, float* __restrict__ C,
    int M, int N, int K) {
    __shared__ float As[8][128];
    __shared__ float Bs[8][128];
    int tid = threadIdx.x;
    int bm = blockIdx.y * 128, bn = blockIdx.x * 128;
    int tx = tid & 15, ty = tid >> 4;
    int trow = ty * 8, tcol = tx * 8;
    float acc[8][8];
#pragma unroll
    for (int i = 0; i < 8; i++)
#pragma unroll
        for (int j = 0; j < 8; j++) acc[i][j] = 0.0f;

    int arow = tid >> 1, ac4 = (tid & 1) * 4;
    int brow = tid >> 5, bc4 = (tid & 31) * 4;
    const float* Aptr = A + (size_t)(bm + arow) * K + ac4;
    const float* Bptr = B + (size_t)brow * N + bn + bc4;

    for (int kb = 0; kb < K; kb += 8) {
        float4 av = *(const float4*)(Aptr + kb);
        float4 bv = *(const float4*)(Bptr + (size_t)kb * N);
        As[ac4 + 0][arow] = av.x;
        As[ac4 + 1][arow] = av.y;
        As[ac4 + 2][arow] = av.z;
        As[ac4 + 3][arow] = av.w;
        *(float4*)&Bs[brow][bc4] = bv;
        __syncthreads();
#pragma unroll
        for (int kk = 0; kk < 8; kk++) {
            float4 a0 = *(const float4*)&As[kk][trow];
            float4 a1 = *(const float4*)&As[kk][trow + 4];
            float4 b0 = *(const float4*)&Bs[kk][tcol];
            float4 b1 = *(const float4*)&Bs[kk][tcol + 4];
            float ar[8] = {a0.x, a0.y, a0.z, a0.w, a1.x, a1.y, a1.z, a1.w};
            float br[8] = {b0.x, b0.y, b0.z, b0.w, b1.x, b1.y, b1.z, b1.w};
#pragma unroll
            for (int i = 0; i < 8; i++)
#pragma unroll
                for (int j = 0; j < 8; j++) acc[i][j] = fmaf(ar[i], br[j], acc[i][j]);
        }
        __syncthreads();
    }
#pragma unroll
    for (int i = 0; i < 8; i++) {
        float* crow = C + (size_t)(bm + trow + i) * N + bn + tcol;
        float4 o0, o1;
        if (DOSILU) {
            o0.x = siluf(acc[i][0]); o0.y = siluf(acc[i][1]);
            o0.z = siluf(acc[i][2]); o0.w = siluf(acc[i][3]);
            o1.x = siluf(acc[i][4]); o1.y = siluf(acc[i][5]);
            o1.z = siluf(acc[i][6]); o1.w = siluf(acc[i][7]);
        } else {
            o0.x = acc[i][0]; o0.y = acc[i][1]; o0.z = acc[i][2]; o0.w = acc[i][3];
            o1.x = acc[i][4]; o1.y = acc[i][5]; o1.z = acc[i][6]; o1.w = acc[i][7];
        }
        *(float4*)crow = o0;
        *(float4*)(crow + 4) = o1;
    }
}

// -------------------- small head projections: beta, exp(g) ----------------
__global__ void proj_bg_k(const float* __restrict__ h, const float* __restrict__ bw,
                          const float* __restrict__ aw, const float* __restrict__ A_log,
                          const float* __restrict__ dt_bias,
                          float* __restrict__ beta, float* __restrict__ eg) {
    int row = blockIdx.x;
    int tid = threadIdx.x;  // 256
    float4 hv = ((const float4*)(h + (size_t)row * CD))[tid];
    float hx[4] = {hv.x, hv.y, hv.z, hv.w};
    float aB[8], aA[8];
#pragma unroll
    for (int j = 0; j < 8; j++) { aB[j] = 0.0f; aA[j] = 0.0f; }
#pragma unroll
    for (int i = 0; i < 4; i++) {
        int kk = tid * 4 + i;
        float xv = hx[i];
        float4 b0 = ((const float4*)(bw + (size_t)kk * CH))[0];
        float4 b1 = ((const float4*)(bw + (size_t)kk * CH))[1];
        float4 a0 = ((const float4*)(aw + (size_t)kk * CH))[0];
        float4 a1 = ((const float4*)(aw + (size_t)kk * CH))[1];
        aB[0] = fmaf(xv, b0.x, aB[0]); aB[1] = fmaf(xv, b0.y, aB[1]);
        aB[2] = fmaf(xv, b0.z, aB[2]); aB[3] = fmaf(xv, b0.w, aB[3]);
        aB[4] = fmaf(xv, b1.x, aB[4]); aB[5] = fmaf(xv, b1.y, aB[5]);
        aB[6] = fmaf(xv, b1.z, aB[6]); aB[7] = fmaf(xv, b1.w, aB[7]);
        aA[0] = fmaf(xv, a0.x, aA[0]); aA[1] = fmaf(xv, a0.y, aA[1]);
        aA[2] = fmaf(xv, a0.z, aA[2]); aA[3] = fmaf(xv, a0.w, aA[3]);
        aA[4] = fmaf(xv, a1.x, aA[4]); aA[5] = fmaf(xv, a1.y, aA[5]);
        aA[6] = fmaf(xv, a1.z, aA[6]); aA[7] = fmaf(xv, a1.w, aA[7]);
    }
#pragma unroll
    for (int j = 0; j < 8; j++) { aB[j] = warpAllSum(aB[j]); aA[j] = warpAllSum(aA[j]); }
    __shared__ float red[8][16];
    int lane = tid & 31, warp = tid >> 5;
    if (lane == 0) {
#pragma unroll
        for (int j = 0; j < 8; j++) { red[warp][j] = aB[j]; red[warp][j + 8] = aA[j]; }
    }
    __syncthreads();
    if (tid < 16) {
        float s = 0.0f;
#pragma unroll
        for (int w = 0; w < 8; w++) s += red[w][tid];
        if (tid < 8) {
            beta[(size_t)row * CH + tid] = 1.0f / (1.0f + expf(-s));
        } else {
            int j = tid - 8;
            float z = s + dt_bias[j];
            float sp = (z > 20.0f) ? z : log1pf(expf(z));
            float g = -expf(A_log[j]) * sp;
            eg[(size_t)row * CH + j] = expf(g);
        }
    }
}

// -------------------- q/k: silu + l2norm per head; v: silu ----------------
__global__ void qkv_act_k(float* __restrict__ q, float* __restrict__ k,
                          float* __restrict__ v) {
    int row = blockIdx.x;
    int lane = threadIdx.x & 31, warp = threadIdx.x >> 5;  // warp = head
    size_t base4 = (size_t)row * (CD / 4) + warp * (CHD / 4) + lane;
    // q
    {
        float4 t = ((float4*)q)[base4];
        t.x = siluf(t.x); t.y = siluf(t.y); t.z = siluf(t.z); t.w = siluf(t.w);
        float ss = warpAllSum(t.x * t.x + t.y * t.y + t.z * t.z + t.w * t.w);
        float sc = rsqrtf(ss + 1e-6f);
        t.x *= sc; t.y *= sc; t.z *= sc; t.w *= sc;
        ((float4*)q)[base4] = t;
    }
    // k
    {
        float4 t = ((float4*)k)[base4];
        t.x = siluf(t.x); t.y = siluf(t.y); t.z = siluf(t.z); t.w = siluf(t.w);
        float ss = warpAllSum(t.x * t.x + t.y * t.y + t.z * t.z + t.w * t.w);
        float sc = rsqrtf(ss + 1e-6f);
        t.x *= sc; t.y *= sc; t.z *= sc; t.w *= sc;
        ((float4*)k)[base4] = t;
    }
    // v
    {
        float4 t = ((float4*)v)[base4];
        t.x = siluf(t.x); t.y = siluf(t.y); t.z = siluf(t.z); t.w = siluf(t.w);
        ((float4*)v)[base4] = t;
    }
}

// -------------------- o = rmsnorm(o, onw) * silu(gate) --------------------
__global__ void onorm_gate_k(float* __restrict__ o, const float* __restrict__ gate,
                             const float* __restrict__ onw) {
    int row = blockIdx.x;
    int lane = threadIdx.x & 31, warp = threadIdx.x >> 5;
    size_t base4 = (size_t)row * (CD / 4) + warp * (CHD / 4) + lane;
    float4 ov = ((float4*)o)[base4];
    float ss = warpAllSum(ov.x * ov.x + ov.y * ov.y + ov.z * ov.z + ov.w * ov.w);
    float sc = rsqrtf(ss * (1.0f / CHD) + 1e-6f);
    float4 gv = ((const float4*)gate)[base4];
    gv.x = siluf(gv.x); gv.y = siluf(gv.y); gv.z = siluf(gv.z); gv.w = siluf(gv.w);
    float4 wv = ((const float4*)onw)[lane];
    float4 r;
    r.x = ov.x * sc * wv.x * gv.x;
    r.y = ov.y * sc * wv.y * gv.y;
    r.z = ov.z * sc * wv.z * gv.z;
    r.w = ov.w * sc * wv.w * gv.w;
    ((float4*)o)[base4] = r;
}

// -------------------- gated delta-rule scan -------------------------------
// grid = 128 CTAs: (b,h) pair x 4 column groups of 32. 256 threads:
// 8 warps; within warp: 4 columns x 8 k-segments (16 k-entries each, in regs).
__global__ __launch_bounds__(256) void scan_k(
    const float* __restrict__ q, const float* __restrict__ k,
    const float* __restrict__ v, const float* __restrict__ beta,
    const float* __restrict__ eg, float* __restrict__ o, float* __restrict__ sf) {
    int bc = blockIdx.x, tid = threadIdx.x;
    int bh = bc >> 2, cg = bc & 3;
    int b = bh >> 3, hh = bh & 7;
    int warp = tid >> 5, lane = tid & 31;
    int col = cg * 32 + warp * 4 + (lane >> 3);
    int seg = lane & 7;

    __shared__ float ksp[136];
    __shared__ float qsp[136];

    float S[16];
#pragma unroll
    for (int j = 0; j < 16; j++) S[j] = 0.0f;

    int rowbase = b * CT * CH + hh;  // idx at t=0
    int u = tid & 127;
    bool isq = tid >= 128;

    // prefetch t = 0
    float kq_reg = isq ? q[(size_t)rowbase * CHD + u] : k[(size_t)rowbase * CHD + u];
    float eg_r = eg[rowbase];
    float bt_r = beta[rowbase];
    float vt_r = v[(size_t)rowbase * CHD + col];

    for (int t = 0; t < CT; t++) {
        int idx = rowbase + t * CH;
        // stage prefetched row into shared
        if (!isq) ksp[u + (u >> 4)] = kq_reg;
        else      qsp[u + (u >> 4)] = kq_reg;
        float egv = eg_r, btv = bt_r, vtv = vt_r;
        __syncthreads();
        // prefetch t+1 (hidden behind compute)
        if (t + 1 < CT) {
            int idx2 = idx + CH;
            kq_reg = isq ? q[(size_t)idx2 * CHD + u] : k[(size_t)idx2 * CHD + u];
            eg_r = eg[idx2];
            bt_r = beta[idx2];
            vt_r = v[(size_t)idx2 * CHD + col];
        }
        // compute
        const float* kp = ksp + seg * 17;
        const float* qp = qsp + seg * 17;
        float kreg[16];
        float kS0 = 0.0f, kS1 = 0.0f;
#pragma unroll
        for (int j = 0; j < 16; j++) {
            float kk = kp[j];
            kreg[j] = kk;
            float s = S[j] * egv;   // Sg
            S[j] = s;
            if (j & 1) kS1 = fmaf(kk, s, kS1);
            else       kS0 = fmaf(kk, s, kS0);
        }
        float kS = kS0 + kS1;
        kS += __shfl_xor_sync(0xffffffffu, kS, 1);
        kS += __shfl_xor_sync(0xffffffffu, kS, 2);
        kS += __shfl_xor_sync(0xffffffffu, kS, 4);
        float bd = btv * (vtv - kS);
        float ot0 = 0.0f, ot1 = 0.0f;
#pragma unroll
        for (int j = 0; j < 16; j++) {
            float s = fmaf(kreg[j], bd, S[j]);  // new state
            S[j] = s;
            if (j & 1) ot1 = fmaf(qp[j], s, ot1);
            else       ot0 = fmaf(qp[j], s, ot0);
        }
        float ot = ot0 + ot1;
        ot += __shfl_xor_sync(0xffffffffu, ot, 1);
        ot += __shfl_xor_sync(0xffffffffu, ot, 2);
        ot += __shfl_xor_sync(0xffffffffu, ot, 4);
        if (seg == 0) o[(size_t)idx * CHD + col] = ot;
        __syncthreads();
    }
    // final state S_f[b, h, k, v]
    float* sfp = sf + ((size_t)(b * CH + hh) * CHD + seg * 16) * CHD + col;
#pragma unroll
    for (int j = 0; j < 16; j++) sfp[(size_t)j * CHD] = S[j];
}

// -------------------- launcher --------------------------------------------
static float* symaddr(const void* sym) {
    void* p = nullptr;
    cudaGetSymbolAddress(&p, sym);
    return (float*)p;
}

extern "C" void kernel_launch(void* const* d_in, const int* in_sizes, int n_in,
                              void* d_out, int out_size) {
    const float* x       = (const float*)d_in[0];
    const float* ln1_w   = (const float*)d_in[1];
    const float* qw      = (const float*)d_in[2];
    const float* kw      = (const float*)d_in[3];
    const float* vw      = (const float*)d_in[4];
    const float* bw      = (const float*)d_in[5];
    const float* aw      = (const float*)d_in[6];
    const float* A_log   = (const float*)d_in[7];
    const float* dt_bias = (const float*)d_in[8];
    const float* gw      = (const float*)d_in[9];
    const float* onorm_w = (const float*)d_in[10];
    const float* ow      = (const float*)d_in[11];
    const float* ln2_w   = (const float*)d_in[12];
    const float* fcw     = (const float*)d_in[13];
    const float* pw      = (const float*)d_in[14];
    float* y = (float*)d_out;

    float* h_    = symaddr(g_h);
    float* q_    = symaddr(g_q);
    float* k_    = symaddr(g_k);
    float* v_    = symaddr(g_v);
    float* gate_ = symaddr(g_gate);
    float* o_    = symaddr(g_o);
    float* attn_ = symaddr(g_attn);
    float* x1_   = symaddr(g_x1);
    float* h2_   = symaddr(g_h2);
    float* m2_   = symaddr(g_m2);
    float* mlp_  = symaddr(g_mlp);
    float* beta_ = symaddr(g_beta);
    float* eg_   = symaddr(g_eg);
    float* sfd_  = symaddr(g_sfdummy);

    float* sfdst = (out_size >= YTOT + STOT) ? (y + YTOT) : sfd_;

    dim3 blk(256);
    dim3 g1024(1024 / 128, CM / 128);   // N=1024 GEMMs
    dim3 g4096(4096 / 128, CM / 128);   // N=4096 GEMM

    // 1. h = rmsnorm(x, ln1_w)
    rmsnorm_k<<<CM, blk>>>(x, ln1_w, h_);
    // 2. projections
    sgemm128<false><<<g1024, blk>>>(h_, qw, q_, CM, CD, CD);
    sgemm128<false><<<g1024, blk>>>(h_, kw, k_, CM, CD, CD);
    sgemm128<false><<<g1024, blk>>>(h_, vw, v_, CM, CD, CD);
    sgemm128<false><<<g1024, blk>>>(h_, gw, gate_, CM, CD, CD);
    // 3. beta, exp(g)
    proj_bg_k<<<CM, blk>>>(h_, bw, aw, A_log, dt_bias, beta_, eg_);
    // 4. activations
    qkv_act_k<<<CM, blk>>>(q_, k_, v_);
    // 5. scan (writes o and S_f)
    scan_k<<<128, blk>>>(q_, k_, v_, beta_, eg_, o_, sfdst);
    // 6. per-head rmsnorm * silu(gate)
    onorm_gate_k<<<CM, blk>>>(o_, gate_, onorm_w);
    // 7. attn = o @ ow
    sgemm128<false><<<g1024, blk>>>(o_, ow, attn_, CM, CD, CD);
    // 8. x1 = x + 0.5*attn ; h2 = rmsnorm(x1, ln2_w)
    resid_rms_k<<<CM, blk>>>(x, attn_, ln2_w, x1_, h2_);
    // 9. mlp = silu(h2 @ fcw)
    sgemm128<true><<<g4096, blk>>>(h2_, fcw, mlp_, CM, 4 * CD, CD);
    // 10. m2 = mlp @ pw
    sgemm128<false><<<g1024, blk>>>(mlp_, pw, m2_, CM, CD, 4 * CD);
    // 11. y = x1 + 0.5*m2
    final_add_k<<<YTOT / 4 / 256, blk>>>(x1_, m2_, y);
}

// round 3
// speedup vs baseline: 1.6959x; 1.6959x over previous
#include <cuda_runtime.h>
#include <cuda_bf16.h>
#include <math.h>

// Problem constants
#define CB 4
#define CT 2048
#define CD 1024
#define CH 8
#define CHD 128
#define CM (CB * CT)          // 8192 rows
#define YTOT (CM * CD)        // 8388608
#define STOT (CB * CH * CHD * CHD)  // 524288
#define RES_SCALE 0.5f

#define W_QW 0
#define W_KW (1024 * 1024)
#define W_VW (2 * 1024 * 1024)
#define W_GW (3 * 1024 * 1024)
#define W_OW (4 * 1024 * 1024)
#define W_FCW (5 * 1024 * 1024)
#define W_PW (9 * 1024 * 1024)
#define W_TOT (13 * 1024 * 1024)

// -------------------- scratch (device globals; no allocations allowed) ----
__device__ float g_h[CM * CD];
__device__ float g_q[CM * CD];
__device__ float g_k[CM * CD];
__device__ float g_v[CM * CD];
__device__ float g_gate[CM * CD];
__device__ float g_o[CM * CD];
__device__ float g_attn[CM * CD];
__device__ float g_x1[CM * CD];
__device__ float g_m2[CM * CD];
__device__ float g_beta[CM * CH];
__device__ float g_eg[CM * CH];
__device__ float g_sfdummy[STOT];

// bf16 hi/lo planes
__device__ __nv_bfloat16 g_hh[CM * CD];
__device__ __nv_bfloat16 g_hl[CM * CD];
__device__ __nv_bfloat16 g_h2h[CM * CD];
__device__ __nv_bfloat16 g_h2l[CM * CD];
__device__ __nv_bfloat16 g_oh[CM * CD];
__device__ __nv_bfloat16 g_ol[CM * CD];
__device__ __nv_bfloat16 g_mlph[CM * 4 * CD];
__device__ __nv_bfloat16 g_mlpl[CM * 4 * CD];
__device__ __nv_bfloat16 g_wth[W_TOT];
__device__ __nv_bfloat16 g_wtl[W_TOT];

// -------------------- helpers --------------------------------------------
__device__ __forceinline__ float siluf(float x) { return x / (1.0f + expf(-x)); }

__device__ __forceinline__ float warpAllSum(float v) {
    v += __shfl_xor_sync(0xffffffffu, v, 16);
    v += __shfl_xor_sync(0xffffffffu, v, 8);
    v += __shfl_xor_sync(0xffffffffu, v, 4);
    v += __shfl_xor_sync(0xffffffffu, v, 2);
    v += __shfl_xor_sync(0xffffffffu, v, 1);
    return v;
}

__device__ __forceinline__ void split_pair(float a, float b,
                                           __nv_bfloat16* hi, __nv_bfloat16* lo) {
    __nv_bfloat16 h0 = __float2bfloat16(a);
    __nv_bfloat16 h1 = __float2bfloat16(b);
    float r0 = a - __bfloat162float(h0);
    float r1 = b - __bfloat162float(h1);
    __nv_bfloat162 hv; hv.x = h0; hv.y = h1;
    __nv_bfloat162 lv; lv.x = __float2bfloat16(r0); lv.y = __float2bfloat16(r1);
    *(__nv_bfloat162*)hi = hv;
    *(__nv_bfloat162*)lo = lv;
}

// -------------------- tensor-core mma wrappers ----------------------------
__device__ __forceinline__ void mma16816(float* c, const unsigned* a, const unsigned* b) {
    asm volatile(
        "mma.sync.aligned.m16n8k16.row.col.f32.bf16.bf16.f32 "
        "{%0,%1,%2,%3},{%4,%5,%6,%7},{%8,%9},{%0,%1,%2,%3};"
        : "+f"(c[0]), "+f"(c[1]), "+f"(c[2]), "+f"(c[3])
        : "r"(a[0]), "r"(a[1]), "r"(a[2]), "r"(a[3]), "r"(b[0]), "r"(b[1]));
}
__device__ __forceinline__ void ldsm4(unsigned* d, unsigned addr) {
    asm volatile("ldmatrix.sync.aligned.m8n8.x4.shared.b16 {%0,%1,%2,%3}, [%4];"
                 : "=r"(d[0]), "=r"(d[1]), "=r"(d[2]), "=r"(d[3]) : "r"(addr));
}
__device__ __forceinline__ void ldsm2(unsigned* d, unsigned addr) {
    asm volatile("ldmatrix.sync.aligned.m8n8.x2.shared.b16 {%0,%1}, [%2];"
                 : "=r"(d[0]), "=r"(d[1]) : "r"(addr));
}

// -------------------- tensor-core GEMM: C = A @ B^T (B stored [N][K]) -----
// A as hi/lo bf16 [M][K]; B as hi/lo bf16 [N][K] (weights pre-transposed).
// EPI 0: write fp32 C. EPI 1: silu then write bf16 hi/lo (Chi/Clo).
#define SSTRIDE 40
template <int EPI>
__global__ __launch_bounds__(256, 2) void gemm_tc(
    const __nv_bfloat16* __restrict__ Ahi, const __nv_bfloat16* __restrict__ Alo,
    const __nv_bfloat16* __restrict__ Bhi, const __nv_bfloat16* __restrict__ Blo,
    float* __restrict__ C, __nv_bfloat16* __restrict__ Chi,
    __nv_bfloat16* __restrict__ Clo, int M, int N, int K) {
    __shared__ __nv_bfloat16 sm[4 * 128 * SSTRIDE];
    __nv_bfloat16* sAh = sm;
    __nv_bfloat16* sAl = sm + 128 * SSTRIDE;
    __nv_bfloat16* sBh = sm + 2 * 128 * SSTRIDE;
    __nv_bfloat16* sBl = sm + 3 * 128 * SSTRIDE;

    int tid = threadIdx.x, warp = tid >> 5, lane = tid & 31;
    int wm = warp >> 2, wn = warp & 3;          // 2 x 4 warp grid, 64x32 tile
    int bm = blockIdx.y * 128, bn = blockIdx.x * 128;

    // gmem loader: 2 threads per row; each thread covers 32B (2 x uint4)
    int lrow = tid >> 1, eoff = (tid & 1) * 16;  // element offset in 32-wide k-tile
    const uint4* gAh = (const uint4*)(Ahi + (size_t)(bm + lrow) * K + eoff);
    const uint4* gAl = (const uint4*)(Alo + (size_t)(bm + lrow) * K + eoff);
    const uint4* gBh = (const uint4*)(Bhi + (size_t)(bn + lrow) * K + eoff);
    const uint4* gBl = (const uint4*)(Blo + (size_t)(bn + lrow) * K + eoff);

    uint4 rAh0 = gAh[0], rAh1 = gAh[1];
    uint4 rAl0 = gAl[0], rAl1 = gAl[1];
    uint4 rBh0 = gBh[0], rBh1 = gBh[1];
    uint4 rBl0 = gBl[0], rBl1 = gBl[1];

    float acc[4][4][4];
#pragma unroll
    for (int i = 0; i < 4; i++)
#pragma unroll
        for (int j = 0; j < 4; j++)
#pragma unroll
            for (int p = 0; p < 4; p++) acc[i][j][p] = 0.0f;

    unsigned bAh = (unsigned)__cvta_generic_to_shared(sAh);
    unsigned bAl = (unsigned)__cvta_generic_to_shared(sAl);
    unsigned bBh = (unsigned)__cvta_generic_to_shared(sBh);
    unsigned bBl = (unsigned)__cvta_generic_to_shared(sBl);

    int sub = lane >> 3, r8 = lane & 7;
    unsigned aoffs = (unsigned)(((wm * 64 + (sub & 1) * 8 + r8) * SSTRIDE + (sub >> 1) * 8) * 2);
    int lb = lane & 15;
    unsigned boffs = (unsigned)(((wn * 32 + (lb & 7)) * SSTRIDE + (lb >> 3) * 8) * 2);

    int srow = lrow * SSTRIDE + eoff;
    for (int kb = 0; kb < K; kb += 32) {
        *(uint4*)&sAh[srow] = rAh0; *(uint4*)&sAh[srow + 8] = rAh1;
        *(uint4*)&sAl[srow] = rAl0; *(uint4*)&sAl[srow + 8] = rAl1;
        *(uint4*)&sBh[srow] = rBh0; *(uint4*)&sBh[srow + 8] = rBh1;
        *(uint4*)&sBl[srow] = rBl0; *(uint4*)&sBl[srow + 8] = rBl1;
        __syncthreads();
        if (kb + 32 < K) {
            int o = (kb + 32) >> 3;
            rAh0 = gAh[o]; rAh1 = gAh[o + 1];
            rAl0 = gAl[o]; rAl1 = gAl[o + 1];
            rBh0 = gBh[o]; rBh1 = gBh[o + 1];
            rBl0 = gBl[o]; rBl1 = gBl[o + 1];
        }
#pragma unroll
        for (int kh = 0; kh < 2; kh++) {
            unsigned bh[4][2], bl[4][2];
#pragma unroll
            for (int ni = 0; ni < 4; ni++) {
                unsigned bo = boffs + (unsigned)((ni * 8 * SSTRIDE + kh * 16) * 2);
                ldsm2(bh[ni], bBh + bo);
                ldsm2(bl[ni], bBl + bo);
            }
#pragma unroll
            for (int mi = 0; mi < 4; mi++) {
                unsigned ah[4], al[4];
                unsigned ao = aoffs + (unsigned)((mi * 16 * SSTRIDE + kh * 16) * 2);
                ldsm4(ah, bAh + ao);
                ldsm4(al, bAl + ao);
#pragma unroll
                for (int ni = 0; ni < 4; ni++) {
                    mma16816(acc[mi][ni], ah, bh[ni]);
                    mma16816(acc[mi][ni], ah, bl[ni]);
                    mma16816(acc[mi][ni], al, bh[ni]);
                }
            }
        }
        __syncthreads();
    }

    int g = lane >> 2, tig = lane & 3;
#pragma unroll
    for (int mi = 0; mi < 4; mi++) {
#pragma unroll
        for (int ni = 0; ni < 4; ni++) {
            int row0 = bm + wm * 64 + mi * 16 + g;
            int col = bn + wn * 32 + ni * 8 + tig * 2;
            if (EPI == 0) {
                float2 t0; t0.x = acc[mi][ni][0]; t0.y = acc[mi][ni][1];
                float2 t1; t1.x = acc[mi][ni][2]; t1.y = acc[mi][ni][3];
                *(float2*)&C[(size_t)row0 * N + col] = t0;
                *(float2*)&C[(size_t)(row0 + 8) * N + col] = t1;
            } else {
                float s0 = siluf(acc[mi][ni][0]), s1 = siluf(acc[mi][ni][1]);
                float s2 = siluf(acc[mi][ni][2]), s3 = siluf(acc[mi][ni][3]);
                split_pair(s0, s1, &Chi[(size_t)row0 * N + col], &Clo[(size_t)row0 * N + col]);
                split_pair(s2, s3, &Chi[(size_t)(row0 + 8) * N + col], &Clo[(size_t)(row0 + 8) * N + col]);
            }
        }
    }
}

// -------------------- weight split + transpose: W[K][N] -> hi/lo [N][K] ---
__global__ void wsplit_t(const float* __restrict__ W, __nv_bfloat16* __restrict__ hi,
                         __nv_bfloat16* __restrict__ lo, int K, int N) {
    __shared__ float tile[32][33];
    int nb = blockIdx.x * 32, kb = blockIdx.y * 32;
    int tx = threadIdx.x & 31, ty = threadIdx.x >> 5;
#pragma unroll
    for (int i = 0; i < 32; i += 8)
        tile[ty + i][tx] = W[(size_t)(kb + ty + i) * N + nb + tx];
    __syncthreads();
#pragma unroll
    for (int i = 0; i < 32; i += 8) {
        float x = tile[tx][ty + i];
        size_t oidx = (size_t)(nb + ty + i) * K + kb + tx;
        __nv_bfloat16 h = __float2bfloat16(x);
        hi[oidx] = h;
        lo[oidx] = __float2bfloat16(x - __bfloat162float(h));
    }
}

// -------------------- rmsnorm (+ bf16 split out) --------------------------
__global__ void rmsnorm_k(const float* __restrict__ x, const float* __restrict__ w,
                          float* __restrict__ out, __nv_bfloat16* __restrict__ ohi,
                          __nv_bfloat16* __restrict__ olo) {
    int row = blockIdx.x;
    int tid = threadIdx.x;
    const float4* x4 = (const float4*)(x + (size_t)row * CD);
    float4 v = x4[tid];
    float ss = v.x * v.x + v.y * v.y + v.z * v.z + v.w * v.w;
    __shared__ float red[8];
    int lane = tid & 31, warp = tid >> 5;
    ss = warpAllSum(ss);
    if (lane == 0) red[warp] = ss;
    __syncthreads();
    float tot = red[0] + red[1] + red[2] + red[3] + red[4] + red[5] + red[6] + red[7];
    float sc = rsqrtf(tot * (1.0f / CD) + 1e-6f);
    float4 wv = ((const float4*)w)[tid];
    float4 o;
    o.x = v.x * wv.x * sc; o.y = v.y * wv.y * sc;
    o.z = v.z * wv.z * sc; o.w = v.w * wv.w * sc;
    if (out) ((float4*)(out + (size_t)row * CD))[tid] = o;
    size_t e = (size_t)row * CD + tid * 4;
    split_pair(o.x, o.y, ohi + e, olo + e);
    split_pair(o.z, o.w, ohi + e + 2, olo + e + 2);
}

// -------- x1 = x + a*0.5 ; h2 = rmsnorm(x1, w) -> bf16 hi/lo only ---------
__global__ void resid_rms_k(const float* __restrict__ x, const float* __restrict__ a,
                            const float* __restrict__ w, float* __restrict__ x1,
                            __nv_bfloat16* __restrict__ h2h, __nv_bfloat16* __restrict__ h2l) {
    int row = blockIdx.x;
    int tid = threadIdx.x;
    float4 xv = ((const float4*)(x + (size_t)row * CD))[tid];
    float4 av = ((const float4*)(a + (size_t)row * CD))[tid];
    float4 v;
    v.x = xv.x + RES_SCALE * av.x; v.y = xv.y + RES_SCALE * av.y;
    v.z = xv.z + RES_SCALE * av.z; v.w = xv.w + RES_SCALE * av.w;
    ((float4*)(x1 + (size_t)row * CD))[tid] = v;
    float ss = v.x * v.x + v.y * v.y + v.z * v.z + v.w * v.w;
    __shared__ float red[8];
    int lane = tid & 31, warp = tid >> 5;
    ss = warpAllSum(ss);
    if (lane == 0) red[warp] = ss;
    __syncthreads();
    float tot = red[0] + red[1] + red[2] + red[3] + red[4] + red[5] + red[6] + red[7];
    float sc = rsqrtf(tot * (1.0f / CD) + 1e-6f);
    float4 wv = ((const float4*)w)[tid];
    float4 o;
    o.x = v.x * wv.x * sc; o.y = v.y * wv.y * sc;
    o.z = v.z * wv.z * sc; o.w = v.w * wv.w * sc;
    size_t e = (size_t)row * CD + tid * 4;
    split_pair(o.x, o.y, h2h + e, h2l + e);
    split_pair(o.z, o.w, h2h + e + 2, h2l + e + 2);
}

// -------------------- y = x1 + m2*0.5 (to d_out) --------------------------
__global__ void final_add_k(const float* __restrict__ x1, const float* __restrict__ m2,
                            float* __restrict__ y) {
    int i = blockIdx.x * blockDim.x + threadIdx.x;
    float4 a = ((const float4*)x1)[i];
    float4 b = ((const float4*)m2)[i];
    float4 o;
    o.x = a.x + RES_SCALE * b.x; o.y = a.y + RES_SCALE * b.y;
    o.z = a.z + RES_SCALE * b.z; o.w = a.w + RES_SCALE * b.w;
    ((float4*)y)[i] = o;
}

// -------------------- small head projections: beta, exp(g) ----------------
__global__ void proj_bg_k(const float* __restrict__ h, const float* __restrict__ bw,
                          const float* __restrict__ aw, const float* __restrict__ A_log,
                          const float* __restrict__ dt_bias,
                          float* __restrict__ beta, float* __restrict__ eg) {
    int row = blockIdx.x;
    int tid = threadIdx.x;
    float4 hv = ((const float4*)(h + (size_t)row * CD))[tid];
    float hx[4] = {hv.x, hv.y, hv.z, hv.w};
    float aB[8], aA[8];
#pragma unroll
    for (int j = 0; j < 8; j++) { aB[j] = 0.0f; aA[j] = 0.0f; }
#pragma unroll
    for (int i = 0; i < 4; i++) {
        int kk = tid * 4 + i;
        float xv = hx[i];
        float4 b0 = ((const float4*)(bw + (size_t)kk * CH))[0];
        float4 b1 = ((const float4*)(bw + (size_t)kk * CH))[1];
        float4 a0 = ((const float4*)(aw + (size_t)kk * CH))[0];
        float4 a1 = ((const float4*)(aw + (size_t)kk * CH))[1];
        aB[0] = fmaf(xv, b0.x, aB[0]); aB[1] = fmaf(xv, b0.y, aB[1]);
        aB[2] = fmaf(xv, b0.z, aB[2]); aB[3] = fmaf(xv, b0.w, aB[3]);
        aB[4] = fmaf(xv, b1.x, aB[4]); aB[5] = fmaf(xv, b1.y, aB[5]);
        aB[6] = fmaf(xv, b1.z, aB[6]); aB[7] = fmaf(xv, b1.w, aB[7]);
        aA[0] = fmaf(xv, a0.x, aA[0]); aA[1] = fmaf(xv, a0.y, aA[1]);
        aA[2] = fmaf(xv, a0.z, aA[2]); aA[3] = fmaf(xv, a0.w, aA[3]);
        aA[4] = fmaf(xv, a1.x, aA[4]); aA[5] = fmaf(xv, a1.y, aA[5]);
        aA[6] = fmaf(xv, a1.z, aA[6]); aA[7] = fmaf(xv, a1.w, aA[7]);
    }
#pragma unroll
    for (int j = 0; j < 8; j++) { aB[j] = warpAllSum(aB[j]); aA[j] = warpAllSum(aA[j]); }
    __shared__ float red[8][16];
    int lane = tid & 31, warp = tid >> 5;
    if (lane == 0) {
#pragma unroll
        for (int j = 0; j < 8; j++) { red[warp][j] = aB[j]; red[warp][j + 8] = aA[j]; }
    }
    __syncthreads();
    if (tid < 16) {
        float s = 0.0f;
#pragma unroll
        for (int w = 0; w < 8; w++) s += red[w][tid];
        if (tid < 8) {
            beta[(size_t)row * CH + tid] = 1.0f / (1.0f + expf(-s));
        } else {
            int j = tid - 8;
            float z = s + dt_bias[j];
            float sp = (z > 20.0f) ? z : log1pf(expf(z));
            float gg = -expf(A_log[j]) * sp;
            eg[(size_t)row * CH + j] = expf(gg);
        }
    }
}

// -------------------- q/k: silu + l2norm per head; v: silu ----------------
__global__ void qkv_act_k(float* __restrict__ q, float* __restrict__ k,
                          float* __restrict__ v) {
    int row = blockIdx.x;
    int lane = threadIdx.x & 31, warp = threadIdx.x >> 5;
    size_t base4 = (size_t)row * (CD / 4) + warp * (CHD / 4) + lane;
    {
        float4 t = ((float4*)q)[base4];
        t.x = siluf(t.x); t.y = siluf(t.y); t.z = siluf(t.z); t.w = siluf(t.w);
        float ss = warpAllSum(t.x * t.x + t.y * t.y + t.z * t.z + t.w * t.w);
        float sc = rsqrtf(ss + 1e-6f);
        t.x *= sc; t.y *= sc; t.z *= sc; t.w *= sc;
        ((float4*)q)[base4] = t;
    }
    {
        float4 t = ((float4*)k)[base4];
        t.x = siluf(t.x); t.y = siluf(t.y); t.z = siluf(t.z); t.w = siluf(t.w);
        float ss = warpAllSum(t.x * t.x + t.y * t.y + t.z * t.z + t.w * t.w);
        float sc = rsqrtf(ss + 1e-6f);
        t.x *= sc; t.y *= sc; t.z *= sc; t.w *= sc;
        ((float4*)k)[base4] = t;
    }
    {
        float4 t = ((float4*)v)[base4];
        t.x = siluf(t.x); t.y = siluf(t.y); t.z = siluf(t.z); t.w = siluf(t.w);
        ((float4*)v)[base4] = t;
    }
}

// --------- o = rmsnorm(o, onw) * silu(gate) -> bf16 hi/lo -----------------
__global__ void onorm_gate_k(const float* __restrict__ o, const float* __restrict__ gate,
                             const float* __restrict__ onw,
                             __nv_bfloat16* __restrict__ oh, __nv_bfloat16* __restrict__ ol) {
    int row = blockIdx.x;
    int lane = threadIdx.x & 31, warp = threadIdx.x >> 5;
    size_t base4 = (size_t)row * (CD / 4) + warp * (CHD / 4) + lane;
    float4 ov = ((const float4*)o)[base4];
    float ss = warpAllSum(ov.x * ov.x + ov.y * ov.y + ov.z * ov.z + ov.w * ov.w);
    float sc = rsqrtf(ss * (1.0f / CHD) + 1e-6f);
    float4 gv = ((const float4*)gate)[base4];
    gv.x = siluf(gv.x); gv.y = siluf(gv.y); gv.z = siluf(gv.z); gv.w = siluf(gv.w);
    float4 wv = ((const float4*)onw)[lane];
    float4 r;
    r.x = ov.x * sc * wv.x * gv.x;
    r.y = ov.y * sc * wv.y * gv.y;
    r.z = ov.z * sc * wv.z * gv.z;
    r.w = ov.w * sc * wv.w * gv.w;
    size_t e = base4 * 4;
    split_pair(r.x, r.y, oh + e, ol + e);
    split_pair(r.z, r.w, oh + e + 2, ol + e + 2);
}

// -------------------- gated delta-rule scan -------------------------------
__global__ __launch_bounds__(256) void scan_k(
    const float* __restrict__ q, const float* __restrict__ k,
    const float* __restrict__ v, const float* __restrict__ beta,
    const float* __restrict__ eg, float* __restrict__ o, float* __restrict__ sf) {
    int bc = blockIdx.x, tid = threadIdx.x;
    int bh = bc >> 2, cg = bc & 3;
    int b = bh >> 3, hh = bh & 7;
    int warp = tid >> 5, lane = tid & 31;
    int col = cg * 32 + warp * 4 + (lane >> 3);
    int seg = lane & 7;

    __shared__ float ksp[136];
    __shared__ float qsp[136];

    float S[16];
#pragma unroll
    for (int j = 0; j < 16; j++) S[j] = 0.0f;

    int rowbase = b * CT * CH + hh;
    int u = tid & 127;
    bool isq = tid >= 128;

    float kq_reg = isq ? q[(size_t)rowbase * CHD + u] : k[(size_t)rowbase * CHD + u];
    float eg_r = eg[rowbase];
    float bt_r = beta[rowbase];
    float vt_r = v[(size_t)rowbase * CHD + col];

    for (int t = 0; t < CT; t++) {
        int idx = rowbase + t * CH;
        if (!isq) ksp[u + (u >> 4)] = kq_reg;
        else      qsp[u + (u >> 4)] = kq_reg;
        float egv = eg_r, btv = bt_r, vtv = vt_r;
        __syncthreads();
        if (t + 1 < CT) {
            int idx2 = idx + CH;
            kq_reg = isq ? q[(size_t)idx2 * CHD + u] : k[(size_t)idx2 * CHD + u];
            eg_r = eg[idx2];
            bt_r = beta[idx2];
            vt_r = v[(size_t)idx2 * CHD + col];
        }
        const float* kp = ksp + seg * 17;
        const float* qp = qsp + seg * 17;
        float kreg[16];
        float kS0 = 0.0f, kS1 = 0.0f;
#pragma unroll
        for (int j = 0; j < 16; j++) {
            float kk = kp[j];
            kreg[j] = kk;
            float s = S[j] * egv;
            S[j] = s;
            if (j & 1) kS1 = fmaf(kk, s, kS1);
            else       kS0 = fmaf(kk, s, kS0);
        }
        float kS = kS0 + kS1;
        kS += __shfl_xor_sync(0xffffffffu, kS, 1);
        kS += __shfl_xor_sync(0xffffffffu, kS, 2);
        kS += __shfl_xor_sync(0xffffffffu, kS, 4);
        float bd = btv * (vtv - kS);
        float ot0 = 0.0f, ot1 = 0.0f;
#pragma unroll
        for (int j = 0; j < 16; j++) {
            float s = fmaf(kreg[j], bd, S[j]);
            S[j] = s;
            if (j & 1) ot1 = fmaf(qp[j], s, ot1);
            else       ot0 = fmaf(qp[j], s, ot0);
        }
        float ot = ot0 + ot1;
        ot += __shfl_xor_sync(0xffffffffu, ot, 1);
        ot += __shfl_xor_sync(0xffffffffu, ot, 2);
        ot += __shfl_xor_sync(0xffffffffu, ot, 4);
        if (seg == 0) o[(size_t)idx * CHD + col] = ot;
        __syncthreads();
    }
    float* sfp = sf + ((size_t)(b * CH + hh) * CHD + seg * 16) * CHD + col;
#pragma unroll
    for (int j = 0; j < 16; j++) sfp[(size_t)j * CHD] = S[j];
}

// -------------------- launcher --------------------------------------------
static float* symaddrf(const void* sym) {
    void* p = nullptr;
    cudaGetSymbolAddress(&p, sym);
    return (float*)p;
}
static __nv_bfloat16* symaddrb(const void* sym) {
    void* p = nullptr;
    cudaGetSymbolAddress(&p, sym);
    return (__nv_bfloat16*)p;
}

extern "C" void kernel_launch(void* const* d_in, const int* in_sizes, int n_in,
                              void* d_out, int out_size) {
    const float* x       = (const float*)d_in[0];
    const float* ln1_w   = (const float*)d_in[1];
    const float* qw      = (const float*)d_in[2];
    const float* kw      = (const float*)d_in[3];
    const float* vw      = (const float*)d_in[4];
    const float* bw      = (const float*)d_in[5];
    const float* aw      = (const float*)d_in[6];
    const float* A_log   = (const float*)d_in[7];
    const float* dt_bias = (const float*)d_in[8];
    const float* gw      = (const float*)d_in[9];
    const float* onorm_w = (const float*)d_in[10];
    const float* ow      = (const float*)d_in[11];
    const float* ln2_w   = (const float*)d_in[12];
    const float* fcw     = (const float*)d_in[13];
    const float* pw      = (const float*)d_in[14];
    float* y = (float*)d_out;

    float* h_    = symaddrf(g_h);
    float* q_    = symaddrf(g_q);
    float* k_    = symaddrf(g_k);
    float* v_    = symaddrf(g_v);
    float* gate_ = symaddrf(g_gate);
    float* o_    = symaddrf(g_o);
    float* attn_ = symaddrf(g_attn);
    float* x1_   = symaddrf(g_x1);
    float* m2_   = symaddrf(g_m2);
    float* beta_ = symaddrf(g_beta);
    float* eg_   = symaddrf(g_eg);
    float* sfd_  = symaddrf(g_sfdummy);

    __nv_bfloat16* hh_   = symaddrb(g_hh);
    __nv_bfloat16* hl_   = symaddrb(g_hl);
    __nv_bfloat16* h2h_  = symaddrb(g_h2h);
    __nv_bfloat16* h2l_  = symaddrb(g_h2l);
    __nv_bfloat16* oh_   = symaddrb(g_oh);
    __nv_bfloat16* ol_   = symaddrb(g_ol);
    __nv_bfloat16* mlph_ = symaddrb(g_mlph);
    __nv_bfloat16* mlpl_ = symaddrb(g_mlpl);
    __nv_bfloat16* wth_  = symaddrb(g_wth);
    __nv_bfloat16* wtl_  = symaddrb(g_wtl);

    float* sfdst = (out_size >= YTOT + STOT) ? (y + YTOT) : sfd_;

    dim3 blk(256);
    dim3 g1024(1024 / 128, CM / 128);
    dim3 g4096(4096 / 128, CM / 128);

    // 0. weight split + transpose (bf16 hi/lo, [N][K])
    wsplit_t<<<dim3(32, 32), blk>>>(qw, wth_ + W_QW, wtl_ + W_QW, 1024, 1024);
    wsplit_t<<<dim3(32, 32), blk>>>(kw, wth_ + W_KW, wtl_ + W_KW, 1024, 1024);
    wsplit_t<<<dim3(32, 32), blk>>>(vw, wth_ + W_VW, wtl_ + W_VW, 1024, 1024);
    wsplit_t<<<dim3(32, 32), blk>>>(gw, wth_ + W_GW, wtl_ + W_GW, 1024, 1024);
    wsplit_t<<<dim3(32, 32), blk>>>(ow, wth_ + W_OW, wtl_ + W_OW, 1024, 1024);
    wsplit_t<<<dim3(128, 32), blk>>>(fcw, wth_ + W_FCW, wtl_ + W_FCW, 1024, 4096);
    wsplit_t<<<dim3(32, 128), blk>>>(pw, wth_ + W_PW, wtl_ + W_PW, 4096, 1024);

    // 1. h = rmsnorm(x)  (fp32 + bf16 hi/lo)
    rmsnorm_k<<<CM, blk>>>(x, ln1_w, h_, hh_, hl_);

    // 2. projections (tensor cores)
    gemm_tc<0><<<g1024, blk>>>(hh_, hl_, wth_ + W_QW, wtl_ + W_QW, q_, nullptr, nullptr, CM, CD, CD);
    gemm_tc<0><<<g1024, blk>>>(hh_, hl_, wth_ + W_KW, wtl_ + W_KW, k_, nullptr, nullptr, CM, CD, CD);
    gemm_tc<0><<<g1024, blk>>>(hh_, hl_, wth_ + W_VW, wtl_ + W_VW, v_, nullptr, nullptr, CM, CD, CD);
    gemm_tc<0><<<g1024, blk>>>(hh_, hl_, wth_ + W_GW, wtl_ + W_GW, gate_, nullptr, nullptr, CM, CD, CD);

    // 3. beta, exp(g)
    proj_bg_k<<<CM, blk>>>(h_, bw, aw, A_log, dt_bias, beta_, eg_);
    // 4. activations
    qkv_act_k<<<CM, blk>>>(q_, k_, v_);
    // 5. scan
    scan_k<<<128, blk>>>(q_, k_, v_, beta_, eg_, o_, sfdst);
    // 6. per-head rmsnorm * silu(gate) -> bf16
    onorm_gate_k<<<CM, blk>>>(o_, gate_, onorm_w, oh_, ol_);
    // 7. attn = o @ ow
    gemm_tc<0><<<g1024, blk>>>(oh_, ol_, wth_ + W_OW, wtl_ + W_OW, attn_, nullptr, nullptr, CM, CD, CD);
    // 8. x1, h2
    resid_rms_k<<<CM, blk>>>(x, attn_, ln2_w, x1_, h2h_, h2l_);
    // 9. mlp = silu(h2 @ fcw) -> bf16 hi/lo only
    gemm_tc<1><<<g4096, blk>>>(h2h_, h2l_, wth_ + W_FCW, wtl_ + W_FCW, nullptr, mlph_, mlpl_, CM, 4 * CD, CD);
    // 10. m2 = mlp @ pw
    gemm_tc<0><<<g1024, blk>>>(mlph_, mlpl_, wth_ + W_PW, wtl_ + W_PW, m2_, nullptr, nullptr, CM, CD, 4 * CD);
    // 11. y = x1 + 0.5*m2
    final_add_k<<<YTOT / 4 / 256, blk>>>(x1_, m2_, y);
}